// round 4
// baseline (speedup 1.0000x reference)
#include <cuda_runtime.h>
#include <math.h>

#define BATCH 8192
#define KL_IDX (8192 * 256)

__device__ float g_xt[256 * BATCH];
__device__ float g_a1[512 * BATCH];
__device__ float g_a2[512 * BATCH];
__device__ float g_part[256];

__constant__ float c_knots[20] = {
    0.f, 0.f, 0.f, 0.f,
    1.f/13, 2.f/13, 3.f/13, 4.f/13, 5.f/13, 6.f/13,
    7.f/13, 8.f/13, 9.f/13, 10.f/13, 11.f/13, 12.f/13,
    1.f, 1.f, 1.f, 1.f
};

// 4 nonzero cubic B-spline values at x (de Boor, clamped uniform knots)
__device__ __forceinline__ void bspline4(float x, int& k0,
                                         float& w0, float& w1, float& w2, float& w3)
{
    x = fminf(fmaxf(x, 0.0f), 1.0f - 1e-6f);
    int s = (int)(x * 13.0f); s = s < 12 ? s : 12;
    k0 = s;
    const int S = s + 3;
    const float l1 = x - c_knots[S],     r1 = c_knots[S + 1] - x;
    const float l2 = x - c_knots[S - 1], r2 = c_knots[S + 2] - x;
    const float l3 = x - c_knots[S - 2], r3 = c_knots[S + 3] - x;
    float t  = __fdividef(1.0f, r1 + l1);
    float n0 = r1 * t, n1 = l1 * t, sv, n2, n3;
    t  = __fdividef(n0, r1 + l2); n0 = r1 * t; sv = l2 * t;
    t  = __fdividef(n1, r2 + l1); n1 = sv + r2 * t; n2 = l1 * t;
    t  = __fdividef(n0, r1 + l3); n0 = r1 * t; sv = l3 * t;
    t  = __fdividef(n1, r2 + l2); n1 = sv + r2 * t; sv = l2 * t;
    t  = __fdividef(n2, r3 + l1); n2 = sv + r3 * t; n3 = l1 * t;
    w0 = n0; w1 = n1; w2 = n2; w3 = n3;
}

typedef unsigned long long u64;
__device__ __forceinline__ u64 dup2(float v)
{ u64 r; asm("mov.b64 %0, {%1, %1};" : "=l"(r) : "f"(v)); return r; }
__device__ __forceinline__ void ffma2(u64& d, u64 a, u64 b)
{ asm("fma.rn.f32x2 %0, %1, %2, %0;" : "+l"(d) : "l"(a), "l"(b)); }
__device__ __forceinline__ void lds2(u64& u0, u64& u1, const float* p)
{ unsigned a = (unsigned)__cvta_generic_to_shared(p);
  asm volatile("ld.shared.v2.u64 {%0, %1}, [%2];" : "=l"(u0), "=l"(u1) : "r"(a)); }
__device__ __forceinline__ float lo32(u64 v) { return __uint_as_float((unsigned)v); }
__device__ __forceinline__ float hi32(u64 v) { return __uint_as_float((unsigned)(v >> 32)); }

// xt: [IN][BATCH]; cm: [OUT][IN*16]; out: trans? [OUT][BATCH] : [BATCH][OUT]
__global__ void __launch_bounds__(256, 2)
kan_gemm(const float* __restrict__ xt, const float* __restrict__ cm,
         float* __restrict__ out, int IN, int OUT, int trans)
{
    __shared__ alignas(16) float As[16][128];
    __shared__ alignas(16) float Bs[16][128];

    const int tid = threadIdx.x;
    const int tx = tid & 15, ty = tid >> 4;
    const int ob = blockIdx.x * 128, bb = blockIdx.y * 128;
    const int K16 = IN * 16;

    u64 acc[8][4];
#pragma unroll
    for (int r = 0; r < 8; ++r)
#pragma unroll
        for (int c = 0; c < 4; ++c) acc[r][c] = 0ull;

    const int o0 = tid >> 1;
    const int kh = (tid & 1) * 8;
    const float* cmp = cm + (size_t)(ob + o0) * K16 + kh;

    float4 cr0 = *(const float4*)(cmp);
    float4 cr1 = *(const float4*)(cmp + 4);
    float xr = (tid < 128) ? xt[bb + tid] : 0.0f;

    // stage i = 0
    Bs[kh+0][o0]=cr0.x; Bs[kh+1][o0]=cr0.y; Bs[kh+2][o0]=cr0.z; Bs[kh+3][o0]=cr0.w;
    Bs[kh+4][o0]=cr1.x; Bs[kh+5][o0]=cr1.y; Bs[kh+6][o0]=cr1.z; Bs[kh+7][o0]=cr1.w;
    if (tid < 128) {
        int k0; float w0, w1, w2, w3;
        bspline4(xr, k0, w0, w1, w2, w3);
#pragma unroll
        for (int k = 0; k < 16; ++k) As[k][tid] = 0.0f;
        As[k0+0][tid]=w0; As[k0+1][tid]=w1; As[k0+2][tid]=w2; As[k0+3][tid]=w3;
    }
    __syncthreads();

    for (int i = 0; i < IN; ++i) {
        const bool more = (i + 1 < IN);
        if (more) {
            const float* p = cmp + (size_t)(i + 1) * 16;
            cr0 = *(const float4*)(p);
            cr1 = *(const float4*)(p + 4);
            if (tid < 128) xr = xt[(size_t)(i + 1) * BATCH + bb + tid];
        }
#pragma unroll
        for (int k = 0; k < 16; ++k) {
            float4 a0 = *(const float4*)&As[k][tx * 4];
            float4 a1 = *(const float4*)&As[k][tx * 4 + 64];
            u64 b0, b1, b2, b3;
            lds2(b0, b1, &Bs[k][ty * 4]);
            lds2(b2, b3, &Bs[k][ty * 4 + 64]);
            u64 ad;
            ad=dup2(a0.x); ffma2(acc[0][0],ad,b0); ffma2(acc[0][1],ad,b1); ffma2(acc[0][2],ad,b2); ffma2(acc[0][3],ad,b3);
            ad=dup2(a0.y); ffma2(acc[1][0],ad,b0); ffma2(acc[1][1],ad,b1); ffma2(acc[1][2],ad,b2); ffma2(acc[1][3],ad,b3);
            ad=dup2(a0.z); ffma2(acc[2][0],ad,b0); ffma2(acc[2][1],ad,b1); ffma2(acc[2][2],ad,b2); ffma2(acc[2][3],ad,b3);
            ad=dup2(a0.w); ffma2(acc[3][0],ad,b0); ffma2(acc[3][1],ad,b1); ffma2(acc[3][2],ad,b2); ffma2(acc[3][3],ad,b3);
            ad=dup2(a1.x); ffma2(acc[4][0],ad,b0); ffma2(acc[4][1],ad,b1); ffma2(acc[4][2],ad,b2); ffma2(acc[4][3],ad,b3);
            ad=dup2(a1.y); ffma2(acc[5][0],ad,b0); ffma2(acc[5][1],ad,b1); ffma2(acc[5][2],ad,b2); ffma2(acc[5][3],ad,b3);
            ad=dup2(a1.z); ffma2(acc[6][0],ad,b0); ffma2(acc[6][1],ad,b1); ffma2(acc[6][2],ad,b2); ffma2(acc[6][3],ad,b3);
            ad=dup2(a1.w); ffma2(acc[7][0],ad,b0); ffma2(acc[7][1],ad,b1); ffma2(acc[7][2],ad,b2); ffma2(acc[7][3],ad,b3);
        }
        __syncthreads();
        if (more) {
            Bs[kh+0][o0]=cr0.x; Bs[kh+1][o0]=cr0.y; Bs[kh+2][o0]=cr0.z; Bs[kh+3][o0]=cr0.w;
            Bs[kh+4][o0]=cr1.x; Bs[kh+5][o0]=cr1.y; Bs[kh+6][o0]=cr1.z; Bs[kh+7][o0]=cr1.w;
            if (tid < 128) {
                int k0; float w0, w1, w2, w3;
                bspline4(xr, k0, w0, w1, w2, w3);
#pragma unroll
                for (int k = 0; k < 16; ++k) As[k][tid] = 0.0f;
                As[k0+0][tid]=w0; As[k0+1][tid]=w1; As[k0+2][tid]=w2; As[k0+3][tid]=w3;
            }
            __syncthreads();
        }
    }

    if (trans) {
#pragma unroll
        for (int c = 0; c < 4; ++c)
#pragma unroll
            for (int h = 0; h < 2; ++h) {
                const int o = ob + ty * 4 + (c & 1) * 2 + h + (c >> 1) * 64;
                float4 v, v2;
                if (h == 0) {
                    v  = make_float4(lo32(acc[0][c]), lo32(acc[1][c]), lo32(acc[2][c]), lo32(acc[3][c]));
                    v2 = make_float4(lo32(acc[4][c]), lo32(acc[5][c]), lo32(acc[6][c]), lo32(acc[7][c]));
                } else {
                    v  = make_float4(hi32(acc[0][c]), hi32(acc[1][c]), hi32(acc[2][c]), hi32(acc[3][c]));
                    v2 = make_float4(hi32(acc[4][c]), hi32(acc[5][c]), hi32(acc[6][c]), hi32(acc[7][c]));
                }
                float* dst = out + (size_t)o * BATCH + bb + tx * 4;
                *(float4*)dst = v;
                *(float4*)(dst + 64) = v2;
            }
    } else {
#pragma unroll
        for (int r = 0; r < 8; ++r) {
            const int b = bb + tx * 4 + (r & 3) + (r >> 2) * 64;
            float4 v  = make_float4(lo32(acc[r][0]), hi32(acc[r][0]), lo32(acc[r][1]), hi32(acc[r][1]));
            float4 v2 = make_float4(lo32(acc[r][2]), hi32(acc[r][2]), lo32(acc[r][3]), hi32(acc[r][3]));
            float* dst = out + (size_t)b * OUT + ob + ty * 4;
            *(float4*)dst = v;
            *(float4*)(dst + 64) = v2;
        }
    }
}

// in[R][C] -> out[C][R], R,C multiples of 32
__global__ void transpose_k(const float* __restrict__ in, float* __restrict__ out, int R, int C)
{
    __shared__ float tile[32][33];
    int c = blockIdx.x * 32 + threadIdx.x;
    int rb = blockIdx.y * 32;
#pragma unroll
    for (int j = 0; j < 32; j += 8)
        tile[threadIdx.y + j][threadIdx.x] = in[(size_t)(rb + threadIdx.y + j) * C + c];
    __syncthreads();
    int c2 = rb + threadIdx.x;
    int r2b = blockIdx.x * 32;
#pragma unroll
    for (int j = 0; j < 32; j += 8)
        out[(size_t)(r2b + threadIdx.y + j) * R + c2] = tile[threadIdx.x][threadIdx.y + j];
}

__global__ void kl_kernel(const float* __restrict__ c0, const float* __restrict__ l0, int n0,
                          const float* __restrict__ c1, const float* __restrict__ l1, int n1,
                          const float* __restrict__ c2, const float* __restrict__ l2, int n2,
                          float* __restrict__ part)
{
    float s = 0.0f;
    const int stride = gridDim.x * blockDim.x;
    const int t0 = blockIdx.x * blockDim.x + threadIdx.x;
    for (int i = t0; i < n0; i += stride) { float c = c0[i], l = l0[i]; s += __expf(l) + c * c - 1.0f - l; }
    for (int i = t0; i < n1; i += stride) { float c = c1[i], l = l1[i]; s += __expf(l) + c * c - 1.0f - l; }
    for (int i = t0; i < n2; i += stride) { float c = c2[i], l = l2[i]; s += __expf(l) + c * c - 1.0f - l; }
    __shared__ float sh[256];
    sh[threadIdx.x] = s;
    __syncthreads();
    for (int o = 128; o > 0; o >>= 1) {
        if (threadIdx.x < o) sh[threadIdx.x] += sh[threadIdx.x + o];
        __syncthreads();
    }
    if (threadIdx.x == 0) part[blockIdx.x] = 0.5f * sh[0];
}

__global__ void kl_final(const float* __restrict__ part, float* __restrict__ dst)
{
    __shared__ float sh[256];
    sh[threadIdx.x] = part[threadIdx.x];
    __syncthreads();
    for (int o = 128; o > 0; o >>= 1) {
        if (threadIdx.x < o) sh[threadIdx.x] += sh[threadIdx.x + o];
        __syncthreads();
    }
    if (threadIdx.x == 0) dst[0] = sh[0];
}

extern "C" void kernel_launch(void* const* d_in, const int* in_sizes, int n_in,
                              void* d_out, int out_size)
{
    const float* x   = (const float*)d_in[0];
    const float* cm0 = (const float*)d_in[1];
    const float* lv0 = (const float*)d_in[2];
    const float* cm1 = (const float*)d_in[3];
    const float* lv1 = (const float*)d_in[4];
    const float* cm2 = (const float*)d_in[5];
    const float* lv2 = (const float*)d_in[6];
    float* out = (float*)d_out;

    float *xt, *a1, *a2, *part;
    cudaGetSymbolAddress((void**)&xt, g_xt);
    cudaGetSymbolAddress((void**)&a1, g_a1);
    cudaGetSymbolAddress((void**)&a2, g_a2);
    cudaGetSymbolAddress((void**)&part, g_part);

    // x [8192][256] -> xt [256][8192]
    transpose_k<<<dim3(256 / 32, BATCH / 32), dim3(32, 8)>>>(x, xt, BATCH, 256);

    kan_gemm<<<dim3(512 / 128, BATCH / 128), 256>>>(xt, cm0, a1, 256, 512, 1);
    kan_gemm<<<dim3(512 / 128, BATCH / 128), 256>>>(a1, cm1, a2, 512, 512, 1);
    kan_gemm<<<dim3(256 / 128, BATCH / 128), 256>>>(a2, cm2, out, 512, 256, 0);

    if (out_size > KL_IDX) {
        kl_kernel<<<256, 256>>>(cm0, lv0, in_sizes[1], cm1, lv1, in_sizes[3],
                                cm2, lv2, in_sizes[5], part);
        kl_final<<<1, 256>>>(part, out + KL_IDX);
    }
}

// round 5
// speedup vs baseline: 1.0463x; 1.0463x over previous
#include <cuda_runtime.h>
#include <math.h>

#define BATCH 8192
#define KL_IDX (8192 * 256)

__device__ float g_xt[256 * BATCH];
__device__ float g_a1[512 * BATCH];
__device__ float g_a2[512 * BATCH];
__device__ float g_part[256];

__constant__ float c_knots[20] = {
    0.f, 0.f, 0.f, 0.f,
    1.f/13, 2.f/13, 3.f/13, 4.f/13, 5.f/13, 6.f/13,
    7.f/13, 8.f/13, 9.f/13, 10.f/13, 11.f/13, 12.f/13,
    1.f, 1.f, 1.f, 1.f
};

// 4 nonzero cubic B-spline values at x (de Boor, clamped uniform knots)
__device__ __forceinline__ void bspline4(float x, int& k0,
                                         float& w0, float& w1, float& w2, float& w3)
{
    x = fminf(fmaxf(x, 0.0f), 1.0f - 1e-6f);
    int s = (int)(x * 13.0f); s = s < 12 ? s : 12;
    k0 = s;
    const int S = s + 3;
    const float l1 = x - c_knots[S],     r1 = c_knots[S + 1] - x;
    const float l2 = x - c_knots[S - 1], r2 = c_knots[S + 2] - x;
    const float l3 = x - c_knots[S - 2], r3 = c_knots[S + 3] - x;
    float t  = __fdividef(1.0f, r1 + l1);
    float n0 = r1 * t, n1 = l1 * t, sv, n2, n3;
    t  = __fdividef(n0, r1 + l2); n0 = r1 * t; sv = l2 * t;
    t  = __fdividef(n1, r2 + l1); n1 = sv + r2 * t; n2 = l1 * t;
    t  = __fdividef(n0, r1 + l3); n0 = r1 * t; sv = l3 * t;
    t  = __fdividef(n1, r2 + l2); n1 = sv + r2 * t; sv = l2 * t;
    t  = __fdividef(n2, r3 + l1); n2 = sv + r3 * t; n3 = l1 * t;
    w0 = n0; w1 = n1; w2 = n2; w3 = n3;
}

typedef unsigned long long u64;
__device__ __forceinline__ u64 dup2(float v)
{ u64 r; asm("mov.b64 %0, {%1, %1};" : "=l"(r) : "f"(v)); return r; }
__device__ __forceinline__ void ffma2(u64& d, u64 a, u64 b)
{ asm("fma.rn.f32x2 %0, %1, %2, %0;" : "+l"(d) : "l"(a), "l"(b)); }
__device__ __forceinline__ void lds2(u64& u0, u64& u1, const float* p)
{ unsigned a = (unsigned)__cvta_generic_to_shared(p);
  asm volatile("ld.shared.v2.u64 {%0, %1}, [%2];" : "=l"(u0), "=l"(u1) : "r"(a)); }
__device__ __forceinline__ float lo32(u64 v) { return __uint_as_float((unsigned)v); }
__device__ __forceinline__ float hi32(u64 v) { return __uint_as_float((unsigned)(v >> 32)); }

// xt: [IN][BATCH]; cm: [OUT][IN*16]; out: trans? [OUT][BATCH] : [BATCH][OUT]
// Block tile: (64*BH) batch rows x 128 outputs. 256 threads, double-buffered smem.
template<int BH>
__global__ void __launch_bounds__(256, 2)
kan_gemm(const float* __restrict__ xt, const float* __restrict__ cm,
         float* __restrict__ out, int IN, int OUT, int trans)
{
    constexpr int TB = 64 * BH;
    __shared__ alignas(16) float As[2][16][TB];
    __shared__ alignas(16) float Bs[2][16][128];

    const int tid = threadIdx.x;
    const int tx = tid & 15, ty = tid >> 4;
    const int ob = blockIdx.x * 128, bb = blockIdx.y * TB;
    const int K16 = IN * 16;

    u64 acc[4 * BH][4];
#pragma unroll
    for (int r = 0; r < 4 * BH; ++r)
#pragma unroll
        for (int c = 0; c < 4; ++c) acc[r][c] = 0ull;

    const int o0 = tid >> 1;
    const int kh = (tid & 1) * 8;
    const float* cmp = cm + (size_t)(ob + o0) * K16 + kh;

    float4 cr0 = *(const float4*)(cmp);
    float4 cr1 = *(const float4*)(cmp + 4);
    float xr = (tid < TB) ? xt[bb + tid] : 0.0f;

    // stage i = 0 into buffer 0
    Bs[0][kh+0][o0]=cr0.x; Bs[0][kh+1][o0]=cr0.y; Bs[0][kh+2][o0]=cr0.z; Bs[0][kh+3][o0]=cr0.w;
    Bs[0][kh+4][o0]=cr1.x; Bs[0][kh+5][o0]=cr1.y; Bs[0][kh+6][o0]=cr1.z; Bs[0][kh+7][o0]=cr1.w;
    if (tid < TB) {
        int k0; float w0, w1, w2, w3;
        bspline4(xr, k0, w0, w1, w2, w3);
#pragma unroll
        for (int k = 0; k < 16; ++k) As[0][k][tid] = 0.0f;
        As[0][k0+0][tid]=w0; As[0][k0+1][tid]=w1; As[0][k0+2][tid]=w2; As[0][k0+3][tid]=w3;
    }
    __syncthreads();

    int p = 0;
    for (int i = 0; i < IN; ++i) {
        const bool more = (i + 1 < IN);
        if (more) {   // prefetch next i into registers (consumed by staging below)
            const float* q = cmp + (size_t)(i + 1) * 16;
            cr0 = *(const float4*)(q);
            cr1 = *(const float4*)(q + 4);
            if (tid < TB) xr = xt[(size_t)(i + 1) * BATCH + bb + tid];
        }
        const float (*Ac)[TB]  = As[p];
        const float (*Bc)[128] = Bs[p];
        const int q = p ^ 1;
        // staging of i+1 into buffer q overlaps the 16 k-step compute on buffer p
        if (more) {
            Bs[q][kh+0][o0]=cr0.x; Bs[q][kh+1][o0]=cr0.y; Bs[q][kh+2][o0]=cr0.z; Bs[q][kh+3][o0]=cr0.w;
            Bs[q][kh+4][o0]=cr1.x; Bs[q][kh+5][o0]=cr1.y; Bs[q][kh+6][o0]=cr1.z; Bs[q][kh+7][o0]=cr1.w;
            if (tid < TB) {
                int k0; float w0, w1, w2, w3;
                bspline4(xr, k0, w0, w1, w2, w3);
#pragma unroll
                for (int k = 0; k < 16; ++k) As[q][k][tid] = 0.0f;
                As[q][k0+0][tid]=w0; As[q][k0+1][tid]=w1; As[q][k0+2][tid]=w2; As[q][k0+3][tid]=w3;
            }
        }
#pragma unroll
        for (int k = 0; k < 16; ++k) {
            float4 a0 = *(const float4*)&Ac[k][tx * 4];
            u64 b0, b1, b2, b3;
            lds2(b0, b1, &Bc[k][ty * 4]);
            lds2(b2, b3, &Bc[k][ty * 4 + 64]);
            u64 ad;
            ad=dup2(a0.x); ffma2(acc[0][0],ad,b0); ffma2(acc[0][1],ad,b1); ffma2(acc[0][2],ad,b2); ffma2(acc[0][3],ad,b3);
            ad=dup2(a0.y); ffma2(acc[1][0],ad,b0); ffma2(acc[1][1],ad,b1); ffma2(acc[1][2],ad,b2); ffma2(acc[1][3],ad,b3);
            ad=dup2(a0.z); ffma2(acc[2][0],ad,b0); ffma2(acc[2][1],ad,b1); ffma2(acc[2][2],ad,b2); ffma2(acc[2][3],ad,b3);
            ad=dup2(a0.w); ffma2(acc[3][0],ad,b0); ffma2(acc[3][1],ad,b1); ffma2(acc[3][2],ad,b2); ffma2(acc[3][3],ad,b3);
            if constexpr (BH == 2) {
                float4 a1 = *(const float4*)&Ac[k][tx * 4 + 64];
                ad=dup2(a1.x); ffma2(acc[4][0],ad,b0); ffma2(acc[4][1],ad,b1); ffma2(acc[4][2],ad,b2); ffma2(acc[4][3],ad,b3);
                ad=dup2(a1.y); ffma2(acc[5][0],ad,b0); ffma2(acc[5][1],ad,b1); ffma2(acc[5][2],ad,b2); ffma2(acc[5][3],ad,b3);
                ad=dup2(a1.z); ffma2(acc[6][0],ad,b0); ffma2(acc[6][1],ad,b1); ffma2(acc[6][2],ad,b2); ffma2(acc[6][3],ad,b3);
                ad=dup2(a1.w); ffma2(acc[7][0],ad,b0); ffma2(acc[7][1],ad,b1); ffma2(acc[7][2],ad,b2); ffma2(acc[7][3],ad,b3);
            }
        }
        __syncthreads();
        p ^= 1;
    }

    if (trans) {
#pragma unroll
        for (int c = 0; c < 4; ++c)
#pragma unroll
            for (int h = 0; h < 2; ++h) {
                const int o = ob + ty * 4 + (c & 1) * 2 + h + (c >> 1) * 64;
                float* dst = out + (size_t)o * BATCH + bb + tx * 4;
                float4 v;
                if (h == 0) v = make_float4(lo32(acc[0][c]), lo32(acc[1][c]), lo32(acc[2][c]), lo32(acc[3][c]));
                else        v = make_float4(hi32(acc[0][c]), hi32(acc[1][c]), hi32(acc[2][c]), hi32(acc[3][c]));
                *(float4*)dst = v;
                if constexpr (BH == 2) {
                    float4 v2;
                    if (h == 0) v2 = make_float4(lo32(acc[4][c]), lo32(acc[5][c]), lo32(acc[6][c]), lo32(acc[7][c]));
                    else        v2 = make_float4(hi32(acc[4][c]), hi32(acc[5][c]), hi32(acc[6][c]), hi32(acc[7][c]));
                    *(float4*)(dst + 64) = v2;
                }
            }
    } else {
#pragma unroll
        for (int r = 0; r < 4 * BH; ++r) {
            const int b = bb + tx * 4 + (r & 3) + (r >> 2) * 64;
            float4 v  = make_float4(lo32(acc[r][0]), hi32(acc[r][0]), lo32(acc[r][1]), hi32(acc[r][1]));
            float4 v2 = make_float4(lo32(acc[r][2]), hi32(acc[r][2]), lo32(acc[r][3]), hi32(acc[r][3]));
            float* dst = out + (size_t)b * OUT + ob + ty * 4;
            *(float4*)dst = v;
            *(float4*)(dst + 64) = v2;
        }
    }
}

// in[R][C] -> out[C][R], R,C multiples of 32
__global__ void transpose_k(const float* __restrict__ in, float* __restrict__ out, int R, int C)
{
    __shared__ float tile[32][33];
    int c = blockIdx.x * 32 + threadIdx.x;
    int rb = blockIdx.y * 32;
#pragma unroll
    for (int j = 0; j < 32; j += 8)
        tile[threadIdx.y + j][threadIdx.x] = in[(size_t)(rb + threadIdx.y + j) * C + c];
    __syncthreads();
    int c2 = rb + threadIdx.x;
    int r2b = blockIdx.x * 32;
#pragma unroll
    for (int j = 0; j < 32; j += 8)
        out[(size_t)(r2b + threadIdx.y + j) * R + c2] = tile[threadIdx.x][threadIdx.y + j];
}

__global__ void kl_kernel(const float* __restrict__ c0, const float* __restrict__ l0, int n0,
                          const float* __restrict__ c1, const float* __restrict__ l1, int n1,
                          const float* __restrict__ c2, const float* __restrict__ l2, int n2,
                          float* __restrict__ part)
{
    float s = 0.0f;
    const int stride = gridDim.x * blockDim.x;
    const int t0 = blockIdx.x * blockDim.x + threadIdx.x;
    for (int i = t0; i < n0; i += stride) { float c = c0[i], l = l0[i]; s += __expf(l) + c * c - 1.0f - l; }
    for (int i = t0; i < n1; i += stride) { float c = c1[i], l = l1[i]; s += __expf(l) + c * c - 1.0f - l; }
    for (int i = t0; i < n2; i += stride) { float c = c2[i], l = l2[i]; s += __expf(l) + c * c - 1.0f - l; }
    __shared__ float sh[256];
    sh[threadIdx.x] = s;
    __syncthreads();
    for (int o = 128; o > 0; o >>= 1) {
        if (threadIdx.x < o) sh[threadIdx.x] += sh[threadIdx.x + o];
        __syncthreads();
    }
    if (threadIdx.x == 0) part[blockIdx.x] = 0.5f * sh[0];
}

__global__ void kl_final(const float* __restrict__ part, float* __restrict__ dst)
{
    __shared__ float sh[256];
    sh[threadIdx.x] = part[threadIdx.x];
    __syncthreads();
    for (int o = 128; o > 0; o >>= 1) {
        if (threadIdx.x < o) sh[threadIdx.x] += sh[threadIdx.x + o];
        __syncthreads();
    }
    if (threadIdx.x == 0) dst[0] = sh[0];
}

extern "C" void kernel_launch(void* const* d_in, const int* in_sizes, int n_in,
                              void* d_out, int out_size)
{
    const float* x   = (const float*)d_in[0];
    const float* cm0 = (const float*)d_in[1];
    const float* lv0 = (const float*)d_in[2];
    const float* cm1 = (const float*)d_in[3];
    const float* lv1 = (const float*)d_in[4];
    const float* cm2 = (const float*)d_in[5];
    const float* lv2 = (const float*)d_in[6];
    float* out = (float*)d_out;

    float *xt, *a1, *a2, *part;
    cudaGetSymbolAddress((void**)&xt, g_xt);
    cudaGetSymbolAddress((void**)&a1, g_a1);
    cudaGetSymbolAddress((void**)&a2, g_a2);
    cudaGetSymbolAddress((void**)&part, g_part);

    // x [8192][256] -> xt [256][8192]
    transpose_k<<<dim3(256 / 32, BATCH / 32), dim3(32, 8)>>>(x, xt, BATCH, 256);

    kan_gemm<2><<<dim3(4, BATCH / 128), 256>>>(xt, cm0, a1, 256, 512, 1);
    kan_gemm<2><<<dim3(4, BATCH / 128), 256>>>(a1, cm1, a2, 512, 512, 1);
    kan_gemm<1><<<dim3(2, BATCH / 64), 256>>>(a2, cm2, out, 512, 256, 0);

    if (out_size > KL_IDX) {
        kl_kernel<<<256, 256>>>(cm0, lv0, in_sizes[1], cm1, lv1, in_sizes[3],
                                cm2, lv2, in_sizes[5], part);
        kl_final<<<1, 256>>>(part, out + KL_IDX);
    }
}

// round 11
// speedup vs baseline: 1.8205x; 1.7399x over previous
#include <cuda_runtime.h>
#include <cuda_fp16.h>
#include <math.h>

#define BATCH 8192
#define KL_IDX (8192 * 256)

#define N0 (512 * 256 * 16)
#define N1 (512 * 512 * 16)
#define N2 (256 * 512 * 16)
#define NTOT (N0 + N1 + N2)

#define LO_SCALE 2048.0f
#define LO_INV   (1.0f / 2048.0f)

__device__ float g_xt[256 * BATCH];
__device__ float g_a1[512 * BATCH];
__device__ float g_a2[512 * BATCH];
__device__ float g_part[256];
__device__ __half g_cmh[NTOT];
__device__ __half g_cml[NTOT];

__constant__ float c_knots[20] = {
    0.f, 0.f, 0.f, 0.f,
    1.f/13, 2.f/13, 3.f/13, 4.f/13, 5.f/13, 6.f/13,
    7.f/13, 8.f/13, 9.f/13, 10.f/13, 11.f/13, 12.f/13,
    1.f, 1.f, 1.f, 1.f
};

// 4 nonzero cubic B-spline values at x (de Boor, clamped uniform knots)
__device__ __forceinline__ void bspline4(float x, int& k0,
                                         float& w0, float& w1, float& w2, float& w3)
{
    x = fminf(fmaxf(x, 0.0f), 1.0f - 1e-6f);
    int s = (int)(x * 13.0f); s = s < 12 ? s : 12;
    k0 = s;
    const int S = s + 3;
    const float l1 = x - c_knots[S],     r1 = c_knots[S + 1] - x;
    const float l2 = x - c_knots[S - 1], r2 = c_knots[S + 2] - x;
    const float l3 = x - c_knots[S - 2], r3 = c_knots[S + 3] - x;
    float t  = __fdividef(1.0f, r1 + l1);
    float n0 = r1 * t, n1 = l1 * t, sv, n2, n3;
    t  = __fdividef(n0, r1 + l2); n0 = r1 * t; sv = l2 * t;
    t  = __fdividef(n1, r2 + l1); n1 = sv + r2 * t; n2 = l1 * t;
    t  = __fdividef(n0, r1 + l3); n0 = r1 * t; sv = l3 * t;
    t  = __fdividef(n1, r2 + l2); n1 = sv + r2 * t; sv = l2 * t;
    t  = __fdividef(n2, r3 + l1); n2 = sv + r3 * t; n3 = l1 * t;
    w0 = n0; w1 = n1; w2 = n2; w3 = n3;
}

// fp16 split: v = h + (l / LO_SCALE); l stored pre-scaled (keeps it fp16-normal)
__device__ __forceinline__ void split2(float v, unsigned short& h, unsigned short& l)
{
    __half hb = __float2half_rn(v);
    float r = (v - __half2float(hb)) * LO_SCALE;
    h = __half_as_ushort(hb);
    l = __half_as_ushort(__float2half_rn(r));
}

typedef unsigned u32;

__device__ __forceinline__ u32 smemu32(const void* p)
{ return (u32)__cvta_generic_to_shared(p); }

__device__ __forceinline__ void sts128(u32 a, u32 x, u32 y, u32 z, u32 w)
{ asm volatile("st.shared.v4.b32 [%0], {%1,%2,%3,%4};" :: "r"(a), "r"(x), "r"(y), "r"(z), "r"(w) : "memory"); }

__device__ __forceinline__ void ldsm4(u32& r0, u32& r1, u32& r2, u32& r3, u32 a)
{ asm volatile("ldmatrix.sync.aligned.m8n8.x4.shared.b16 {%0,%1,%2,%3}, [%4];"
               : "=r"(r0), "=r"(r1), "=r"(r2), "=r"(r3) : "r"(a)); }

__device__ __forceinline__ void mma_f16(float* c, const u32* a, u32 b0, u32 b1)
{
    asm volatile("mma.sync.aligned.m16n8k16.row.col.f32.f16.f16.f32 "
        "{%0,%1,%2,%3}, {%4,%5,%6,%7}, {%8,%9}, {%0,%1,%2,%3};"
        : "+f"(c[0]), "+f"(c[1]), "+f"(c[2]), "+f"(c[3])
        : "r"(a[0]), "r"(a[1]), "r"(a[2]), "r"(a[3]), "r"(b0), "r"(b1));
}

// smem geometry: rows padded to 48B (conflict-free ldmatrix + STS); 16B slab skew
#define ROWP 48
#define SLAB (128 * ROWP + 16)
#define REG4 (4 * SLAB)
#define R_AH 0
#define R_AL (REG4)
#define R_BH (2 * REG4)
#define R_BL (3 * REG4)
#define SMEM_TOT (4 * REG4)

// ---------------------------------------------------------------------------
// Fused KAN layer via warp-level fp16 HMMA, 2-plane split with scaled lo,
// dual fp32 accumulators (main + correction).
//   xt : [IN][BATCH] fp32; cmh/cml : [OUT][IN*16] fp16 (lo pre-scaled 2^11)
//   out: TRANS ? [OUT][BATCH] : [BATCH][OUT]
// CTA: 128 batch x 128 out, 512 threads (16 warps, 4x4), 2 features/iter.
// ---------------------------------------------------------------------------
template<int TRANS>
__global__ void __launch_bounds__(512, 1)
kan_hmma(const float* __restrict__ xt, const __half* __restrict__ cmh,
         const __half* __restrict__ cml, float* __restrict__ out, int IN, int OUT)
{
    extern __shared__ unsigned char smem[];
    const u32 s = smemu32(smem);

    const int tid = threadIdx.x;
    const int wid = tid >> 5, lane = tid & 31;
    const int warp_m = wid & 3, warp_n = wid >> 2;
    const int ob = blockIdx.x * 128, bb = blockIdx.y * 128;
    const int K16 = IN * 16;

    // B-staging: each thread owns one 16B chunk per plane
    const int sn = tid >> 2, sfeat = (tid >> 1) & 1, shalf = tid & 1;
    // A-staging (tid < 256)
    const int arow = tid & 127, afeat = (tid >> 7) & 1;

    // fragment base offsets (within a slab)
    const u32 a_off = (u32)((warp_m * 32 + (lane & 7) + ((lane >> 3) & 1) * 8) * ROWP
                            + (lane >> 4) * 16);
    const u32 b_off = (u32)((warp_n * 32 + (lane & 7) + (lane >> 4) * 8) * ROWP
                            + ((lane >> 3) & 1) * 16);

    float accm[2][4][4];   // hi*hi
    float accc[2][4][4];   // hi*lo' + lo'*hi  (scaled by LO_SCALE)
#pragma unroll
    for (int mi = 0; mi < 2; ++mi)
#pragma unroll
        for (int nt = 0; nt < 4; ++nt)
#pragma unroll
            for (int r = 0; r < 4; ++r) { accm[mi][nt][r] = 0.0f; accc[mi][nt][r] = 0.0f; }

    uint4 pvh, pvl;          // prefetched cm chunks
    float px = 0.0f;         // prefetched activation (tid < 256)

    auto prefetch = [&](int i0) {
        const size_t g = (size_t)(ob + sn) * K16 + (size_t)(i0 + sfeat) * 16 + shalf * 8;
        pvh = *(const uint4*)(cmh + g);
        pvl = *(const uint4*)(cml + g);
        if (tid < 256) px = xt[(size_t)(i0 + afeat) * BATCH + bb + arow];
    };

    auto stage = [&](int buf) {
        const u32 bslab = (u32)((buf * 2 + sfeat) * SLAB);
        const u32 ba = (u32)(sn * ROWP + shalf * 16);
        sts128(s + R_BH + bslab + ba, pvh.x, pvh.y, pvh.z, pvh.w);
        sts128(s + R_BL + bslab + ba, pvl.x, pvl.y, pvl.z, pvl.w);
        if (tid < 256) {
            int k0; float w0, w1, w2, w3;
            bspline4(px, k0, w0, w1, w2, w3);
            unsigned short hb[4], lb[4];
            float wv[4] = {w0, w1, w2, w3};
#pragma unroll
            for (int j = 0; j < 4; ++j) split2(wv[j], hb[j], lb[j]);
            const int e = k0 & 1, base = k0 >> 1;
            u32 h0, h1, h2, l0, l1, l2;
            if (e == 0) { h0 = hb[0] | ((u32)hb[1] << 16); h1 = hb[2] | ((u32)hb[3] << 16); h2 = 0;
                          l0 = lb[0] | ((u32)lb[1] << 16); l1 = lb[2] | ((u32)lb[3] << 16); l2 = 0; }
            else        { h0 = (u32)hb[0] << 16; h1 = hb[1] | ((u32)hb[2] << 16); h2 = hb[3];
                          l0 = (u32)lb[0] << 16; l1 = lb[1] | ((u32)lb[2] << 16); l2 = lb[3]; }
            u32 WH[8], WL[8];
#pragma unroll
            for (int w = 0; w < 8; ++w) {
                WH[w] = (w == base) ? h0 : (w == base + 1) ? h1 : (w == base + 2) ? h2 : 0;
                WL[w] = (w == base) ? l0 : (w == base + 1) ? l1 : (w == base + 2) ? l2 : 0;
            }
            const u32 aslab = (u32)((buf * 2 + afeat) * SLAB);
            const u32 aa = (u32)(arow * ROWP);
            sts128(s + R_AH + aslab + aa,      WH[0], WH[1], WH[2], WH[3]);
            sts128(s + R_AH + aslab + aa + 16, WH[4], WH[5], WH[6], WH[7]);
            sts128(s + R_AL + aslab + aa,      WL[0], WL[1], WL[2], WL[3]);
            sts128(s + R_AL + aslab + aa + 16, WL[4], WL[5], WL[6], WL[7]);
        }
    };

    prefetch(0);
    stage(0);
    __syncthreads();

    int p = 0;
    for (int i0 = 0; i0 < IN; i0 += 2) {
        const bool more = (i0 + 2 < IN);
        if (more) prefetch(i0 + 2);

        // ---- compute on buffer p (2 features) ----
#pragma unroll
        for (int f = 0; f < 2; ++f) {
            const u32 sl = (u32)((p * 2 + f) * SLAB);
            u32 ah[2][4], al[2][4], bh[4][2], bl[4][2];
#pragma unroll
            for (int mi = 0; mi < 2; ++mi) {
                const u32 ao = sl + a_off + (u32)(mi * 16 * ROWP);
                ldsm4(ah[mi][0], ah[mi][1], ah[mi][2], ah[mi][3], s + R_AH + ao);
                ldsm4(al[mi][0], al[mi][1], al[mi][2], al[mi][3], s + R_AL + ao);
            }
#pragma unroll
            for (int nj = 0; nj < 2; ++nj) {
                const u32 bo = sl + b_off + (u32)(nj * 16 * ROWP);
                ldsm4(bh[2*nj][0], bh[2*nj][1], bh[2*nj+1][0], bh[2*nj+1][1], s + R_BH + bo);
                ldsm4(bl[2*nj][0], bl[2*nj][1], bl[2*nj+1][0], bl[2*nj+1][1], s + R_BL + bo);
            }
#pragma unroll
            for (int mi = 0; mi < 2; ++mi)
#pragma unroll
                for (int nt = 0; nt < 4; ++nt) {
                    mma_f16(accm[mi][nt], ah[mi], bh[nt][0], bh[nt][1]);
                    mma_f16(accc[mi][nt], ah[mi], bl[nt][0], bl[nt][1]);
                    mma_f16(accc[mi][nt], al[mi], bh[nt][0], bh[nt][1]);
                }
        }

        if (more) stage(p ^ 1);
        __syncthreads();
        p ^= 1;
    }

    // ---- epilogue: combine main + scaled correction ----
    const int row0 = bb + warp_m * 32 + (lane >> 2);
    const int col0 = ob + warp_n * 32 + (lane & 3) * 2;
#pragma unroll
    for (int mi = 0; mi < 2; ++mi)
#pragma unroll
        for (int nt = 0; nt < 4; ++nt) {
            const int r = row0 + mi * 16;
            const int c = col0 + nt * 8;
            float v0 = fmaf(accc[mi][nt][0], LO_INV, accm[mi][nt][0]);
            float v1 = fmaf(accc[mi][nt][1], LO_INV, accm[mi][nt][1]);
            float v2 = fmaf(accc[mi][nt][2], LO_INV, accm[mi][nt][2]);
            float v3 = fmaf(accc[mi][nt][3], LO_INV, accm[mi][nt][3]);
            if (TRANS) {
                out[(size_t)c * BATCH + r]           = v0;
                out[(size_t)(c + 1) * BATCH + r]     = v1;
                out[(size_t)c * BATCH + r + 8]       = v2;
                out[(size_t)(c + 1) * BATCH + r + 8] = v3;
            } else {
                *(float2*)(out + (size_t)r * OUT + c)       = make_float2(v0, v1);
                *(float2*)(out + (size_t)(r + 8) * OUT + c) = make_float2(v2, v3);
            }
        }
}

// ---------------------------------------------------------------------------
__global__ void cvt_cm(const float* __restrict__ src, __half* __restrict__ h,
                       __half* __restrict__ l, int n)
{
    const int stride = gridDim.x * blockDim.x;
    for (int i = blockIdx.x * blockDim.x + threadIdx.x; i < n; i += stride) {
        unsigned short hv, lv;
        split2(src[i], hv, lv);
        h[i] = __ushort_as_half(hv);
        l[i] = __ushort_as_half(lv);
    }
}

// in[R][C] -> out[C][R]
__global__ void transpose_k(const float* __restrict__ in, float* __restrict__ out, int R, int C)
{
    __shared__ float tile[32][33];
    int c = blockIdx.x * 32 + threadIdx.x;
    int rb = blockIdx.y * 32;
#pragma unroll
    for (int j = 0; j < 32; j += 8)
        tile[threadIdx.y + j][threadIdx.x] = in[(size_t)(rb + threadIdx.y + j) * C + c];
    __syncthreads();
    int c2 = rb + threadIdx.x;
    int r2b = blockIdx.x * 32;
#pragma unroll
    for (int j = 0; j < 32; j += 8)
        out[(size_t)(r2b + threadIdx.y + j) * R + c2] = tile[threadIdx.x][threadIdx.y + j];
}

__global__ void kl_kernel(const float* __restrict__ c0, const float* __restrict__ l0, int n0,
                          const float* __restrict__ c1, const float* __restrict__ l1, int n1,
                          const float* __restrict__ c2, const float* __restrict__ l2, int n2,
                          float* __restrict__ part)
{
    float sacc = 0.0f;
    const int stride = gridDim.x * blockDim.x;
    const int t0 = blockIdx.x * blockDim.x + threadIdx.x;
    for (int i = t0; i < n0; i += stride) { float c = c0[i], l = l0[i]; sacc += __expf(l) + c * c - 1.0f - l; }
    for (int i = t0; i < n1; i += stride) { float c = c1[i], l = l1[i]; sacc += __expf(l) + c * c - 1.0f - l; }
    for (int i = t0; i < n2; i += stride) { float c = c2[i], l = l2[i]; sacc += __expf(l) + c * c - 1.0f - l; }
    __shared__ float sh[256];
    sh[threadIdx.x] = sacc;
    __syncthreads();
    for (int o = 128; o > 0; o >>= 1) {
        if (threadIdx.x < o) sh[threadIdx.x] += sh[threadIdx.x + o];
        __syncthreads();
    }
    if (threadIdx.x == 0) part[blockIdx.x] = 0.5f * sh[0];
}

__global__ void kl_final(const float* __restrict__ part, float* __restrict__ dst)
{
    __shared__ float sh[256];
    sh[threadIdx.x] = part[threadIdx.x];
    __syncthreads();
    for (int o = 128; o > 0; o >>= 1) {
        if (threadIdx.x < o) sh[threadIdx.x] += sh[threadIdx.x + o];
        __syncthreads();
    }
    if (threadIdx.x == 0) dst[0] = sh[0];
}

extern "C" void kernel_launch(void* const* d_in, const int* in_sizes, int n_in,
                              void* d_out, int out_size)
{
    const float* x   = (const float*)d_in[0];
    const float* cm0 = (const float*)d_in[1];
    const float* lv0 = (const float*)d_in[2];
    const float* cm1 = (const float*)d_in[3];
    const float* lv1 = (const float*)d_in[4];
    const float* cm2 = (const float*)d_in[5];
    const float* lv2 = (const float*)d_in[6];
    float* out = (float*)d_out;

    float *xt, *a1, *a2, *part;
    __half *cmh, *cml;
    cudaGetSymbolAddress((void**)&xt, g_xt);
    cudaGetSymbolAddress((void**)&a1, g_a1);
    cudaGetSymbolAddress((void**)&a2, g_a2);
    cudaGetSymbolAddress((void**)&part, g_part);
    cudaGetSymbolAddress((void**)&cmh, g_cmh);
    cudaGetSymbolAddress((void**)&cml, g_cml);

    cudaFuncSetAttribute(kan_hmma<1>, cudaFuncAttributeMaxDynamicSharedMemorySize, SMEM_TOT);
    cudaFuncSetAttribute(kan_hmma<0>, cudaFuncAttributeMaxDynamicSharedMemorySize, SMEM_TOT);

    // split cm into fp16 hi + scaled lo
    cvt_cm<<<256, 256>>>(cm0, cmh,           cml,           N0);
    cvt_cm<<<256, 256>>>(cm1, cmh + N0,      cml + N0,      N1);
    cvt_cm<<<256, 256>>>(cm2, cmh + N0 + N1, cml + N0 + N1, N2);

    // x [8192][256] -> xt [256][8192]
    transpose_k<<<dim3(8, 256), dim3(32, 8)>>>(x, xt, BATCH, 256);

    kan_hmma<1><<<dim3(4, 64), 512, SMEM_TOT>>>(xt, cmh,           cml,           a1, 256, 512);
    kan_hmma<1><<<dim3(4, 64), 512, SMEM_TOT>>>(a1, cmh + N0,      cml + N0,      a2, 512, 512);
    kan_hmma<0><<<dim3(2, 64), 512, SMEM_TOT>>>(a2, cmh + N0 + N1, cml + N0 + N1, out, 512, 256);

    if (out_size > KL_IDX) {
        kl_kernel<<<256, 256>>>(cm0, lv0, in_sizes[1], cm1, lv1, in_sizes[3],
                                cm2, lv2, in_sizes[5], part);
        kl_final<<<1, 256>>>(part, out + KL_IDX);
    }
}

// round 12
// speedup vs baseline: 2.1312x; 1.1707x over previous
#include <cuda_runtime.h>
#include <cuda_fp16.h>
#include <math.h>

#define BATCH 8192
#define KL_IDX (8192 * 256)

#define N0 (512 * 256 * 16)
#define N1 (512 * 512 * 16)
#define N2 (256 * 512 * 16)
#define NTOT (N0 + N1 + N2)

#define LO_SCALE 2048.0f
#define LO_INV   (1.0f / 2048.0f)

__device__ float g_xt[256 * BATCH];
__device__ float g_a1[512 * BATCH];
__device__ float g_a2[512 * BATCH];
__device__ float g_part[256];
__device__ __half g_cmh[NTOT];
__device__ __half g_cml[NTOT];

__constant__ float c_knots[20] = {
    0.f, 0.f, 0.f, 0.f,
    1.f/13, 2.f/13, 3.f/13, 4.f/13, 5.f/13, 6.f/13,
    7.f/13, 8.f/13, 9.f/13, 10.f/13, 11.f/13, 12.f/13,
    1.f, 1.f, 1.f, 1.f
};

// 4 nonzero cubic B-spline values at x (de Boor, clamped uniform knots)
__device__ __forceinline__ void bspline4(float x, int& k0,
                                         float& w0, float& w1, float& w2, float& w3)
{
    x = fminf(fmaxf(x, 0.0f), 1.0f - 1e-6f);
    int s = (int)(x * 13.0f); s = s < 12 ? s : 12;
    k0 = s;
    const int S = s + 3;
    const float l1 = x - c_knots[S],     r1 = c_knots[S + 1] - x;
    const float l2 = x - c_knots[S - 1], r2 = c_knots[S + 2] - x;
    const float l3 = x - c_knots[S - 2], r3 = c_knots[S + 3] - x;
    float t  = __fdividef(1.0f, r1 + l1);
    float n0 = r1 * t, n1 = l1 * t, sv, n2, n3;
    t  = __fdividef(n0, r1 + l2); n0 = r1 * t; sv = l2 * t;
    t  = __fdividef(n1, r2 + l1); n1 = sv + r2 * t; n2 = l1 * t;
    t  = __fdividef(n0, r1 + l3); n0 = r1 * t; sv = l3 * t;
    t  = __fdividef(n1, r2 + l2); n1 = sv + r2 * t; sv = l2 * t;
    t  = __fdividef(n2, r3 + l1); n2 = sv + r3 * t; n3 = l1 * t;
    w0 = n0; w1 = n1; w2 = n2; w3 = n3;
}

// fp16 split: v = h + (l / LO_SCALE); l stored pre-scaled (keeps it fp16-normal)
__device__ __forceinline__ void split2(float v, unsigned short& h, unsigned short& l)
{
    __half hb = __float2half_rn(v);
    float r = (v - __half2float(hb)) * LO_SCALE;
    h = __half_as_ushort(hb);
    l = __half_as_ushort(__float2half_rn(r));
}

typedef unsigned u32;

__device__ __forceinline__ u32 smemu32(const void* p)
{ return (u32)__cvta_generic_to_shared(p); }

__device__ __forceinline__ void sts128(u32 a, u32 x, u32 y, u32 z, u32 w)
{ asm volatile("st.shared.v4.b32 [%0], {%1,%2,%3,%4};" :: "r"(a), "r"(x), "r"(y), "r"(z), "r"(w) : "memory"); }

__device__ __forceinline__ void ldsm4(u32& r0, u32& r1, u32& r2, u32& r3, u32 a)
{ asm volatile("ldmatrix.sync.aligned.m8n8.x4.shared.b16 {%0,%1,%2,%3}, [%4];"
               : "=r"(r0), "=r"(r1), "=r"(r2), "=r"(r3) : "r"(a)); }

__device__ __forceinline__ void mma_f16(float* c, const u32* a, u32 b0, u32 b1)
{
    asm volatile("mma.sync.aligned.m16n8k16.row.col.f32.f16.f16.f32 "
        "{%0,%1,%2,%3}, {%4,%5,%6,%7}, {%8,%9}, {%0,%1,%2,%3};"
        : "+f"(c[0]), "+f"(c[1]), "+f"(c[2]), "+f"(c[3])
        : "r"(a[0]), "r"(a[1]), "r"(a[2]), "r"(a[3]), "r"(b0), "r"(b1));
}

// smem geometry: 48B row pitch (conflict-free ldmatrix + STS); 16B slab skew
#define ROWP  48
#define ASLAB (64 * ROWP + 16)     // A tile: 64 batch rows
#define BSLAB (128 * ROWP + 16)    // B tile: 128 out rows
#define R_AH  0
#define R_AL  (4 * ASLAB)
#define R_BH  (8 * ASLAB)
#define R_BL  (8 * ASLAB + 4 * BSLAB)
#define SMEM_TOT (8 * ASLAB + 8 * BSLAB)

// ---------------------------------------------------------------------------
// Fused KAN layer via warp-level fp16 HMMA, 2-plane split with scaled lo,
// dual fp32 accumulators (main + correction).
//   xt : [IN][BATCH] fp32; cmh/cml : [OUT][IN*16] fp16 (lo pre-scaled 2^11)
//   out: TRANS ? [OUT][BATCH] : [BATCH][OUT]
// CTA: 64 batch x 128 out, 256 threads (8 warps, 2x4), 2 features/iter,
// double-buffered, 2 CTAs/SM.
// ---------------------------------------------------------------------------
template<int TRANS>
__global__ void __launch_bounds__(256, 2)
kan_hmma(const float* __restrict__ xt, const __half* __restrict__ cmh,
         const __half* __restrict__ cml, float* __restrict__ out, int IN, int OUT)
{
    extern __shared__ unsigned char smem[];
    const u32 s = smemu32(smem);

    const int tid = threadIdx.x;
    const int wid = tid >> 5, lane = tid & 31;
    const int warp_m = wid & 1, warp_n = wid >> 1;
    const int ob = blockIdx.x * 128, bb = blockIdx.y * 64;
    const int K16 = IN * 16;

    // A-staging (tid < 128): one row per (row, feat)
    const int arow = tid & 63, afeat = (tid >> 6) & 1;

    // fragment base offsets (within a slab)
    const u32 a_off = (u32)((warp_m * 32 + (lane & 7) + ((lane >> 3) & 1) * 8) * ROWP
                            + (lane >> 4) * 16);
    const u32 b_off = (u32)((warp_n * 32 + (lane & 7) + (lane >> 4) * 8) * ROWP
                            + ((lane >> 3) & 1) * 16);

    float accm[2][4][4];   // hi*hi
    float accc[2][4][4];   // hi*lo' + lo'*hi  (scaled by LO_SCALE)
#pragma unroll
    for (int mi = 0; mi < 2; ++mi)
#pragma unroll
        for (int nt = 0; nt < 4; ++nt)
#pragma unroll
            for (int r = 0; r < 4; ++r) { accm[mi][nt][r] = 0.0f; accc[mi][nt][r] = 0.0f; }

    uint4 pvh[2], pvl[2];    // prefetched cm chunks (2 per thread)
    float px = 0.0f;         // prefetched activation (tid < 128)

    auto prefetch = [&](int i0) {
#pragma unroll
        for (int j = 0; j < 2; ++j) {
            const int c = tid + j * 256;
            const int cn = c >> 2, cfeat = (c >> 1) & 1, chalf = c & 1;
            const size_t g = (size_t)(ob + cn) * K16 + (size_t)(i0 + cfeat) * 16 + chalf * 8;
            pvh[j] = *(const uint4*)(cmh + g);
            pvl[j] = *(const uint4*)(cml + g);
        }
        if (tid < 128) px = xt[(size_t)(i0 + afeat) * BATCH + bb + arow];
    };

    auto stage = [&](int buf) {
#pragma unroll
        for (int j = 0; j < 2; ++j) {
            const int c = tid + j * 256;
            const int cn = c >> 2, cfeat = (c >> 1) & 1, chalf = c & 1;
            const u32 bslab = (u32)((buf * 2 + cfeat) * BSLAB);
            const u32 ba = (u32)(cn * ROWP + chalf * 16);
            sts128(s + R_BH + bslab + ba, pvh[j].x, pvh[j].y, pvh[j].z, pvh[j].w);
            sts128(s + R_BL + bslab + ba, pvl[j].x, pvl[j].y, pvl[j].z, pvl[j].w);
        }
        if (tid < 128) {
            int k0; float w0, w1, w2, w3;
            bspline4(px, k0, w0, w1, w2, w3);
            unsigned short hb[4], lb[4];
            float wv[4] = {w0, w1, w2, w3};
#pragma unroll
            for (int j = 0; j < 4; ++j) split2(wv[j], hb[j], lb[j]);
            const int e = k0 & 1, base = k0 >> 1;
            u32 h0, h1, h2, l0, l1, l2;
            if (e == 0) { h0 = hb[0] | ((u32)hb[1] << 16); h1 = hb[2] | ((u32)hb[3] << 16); h2 = 0;
                          l0 = lb[0] | ((u32)lb[1] << 16); l1 = lb[2] | ((u32)lb[3] << 16); l2 = 0; }
            else        { h0 = (u32)hb[0] << 16; h1 = hb[1] | ((u32)hb[2] << 16); h2 = hb[3];
                          l0 = (u32)lb[0] << 16; l1 = lb[1] | ((u32)lb[2] << 16); l2 = lb[3]; }
            u32 WH[8], WL[8];
#pragma unroll
            for (int w = 0; w < 8; ++w) {
                WH[w] = (w == base) ? h0 : (w == base + 1) ? h1 : (w == base + 2) ? h2 : 0;
                WL[w] = (w == base) ? l0 : (w == base + 1) ? l1 : (w == base + 2) ? l2 : 0;
            }
            const u32 aslab = (u32)((buf * 2 + afeat) * ASLAB);
            const u32 aa = (u32)(arow * ROWP);
            sts128(s + R_AH + aslab + aa,      WH[0], WH[1], WH[2], WH[3]);
            sts128(s + R_AH + aslab + aa + 16, WH[4], WH[5], WH[6], WH[7]);
            sts128(s + R_AL + aslab + aa,      WL[0], WL[1], WL[2], WL[3]);
            sts128(s + R_AL + aslab + aa + 16, WL[4], WL[5], WL[6], WL[7]);
        }
    };

    prefetch(0);
    stage(0);
    __syncthreads();

    int p = 0;
    for (int i0 = 0; i0 < IN; i0 += 2) {
        const bool more = (i0 + 2 < IN);
        if (more) prefetch(i0 + 2);

        // ---- compute on buffer p (2 features) ----
#pragma unroll
        for (int f = 0; f < 2; ++f) {
            const u32 sla = (u32)((p * 2 + f) * ASLAB);
            const u32 slb = (u32)((p * 2 + f) * BSLAB);
            u32 ah[2][4], al[2][4], bh[4][2], bl[4][2];
#pragma unroll
            for (int mi = 0; mi < 2; ++mi) {
                const u32 ao = sla + a_off + (u32)(mi * 16 * ROWP);
                ldsm4(ah[mi][0], ah[mi][1], ah[mi][2], ah[mi][3], s + R_AH + ao);
                ldsm4(al[mi][0], al[mi][1], al[mi][2], al[mi][3], s + R_AL + ao);
            }
#pragma unroll
            for (int nj = 0; nj < 2; ++nj) {
                const u32 bo = slb + b_off + (u32)(nj * 16 * ROWP);
                ldsm4(bh[2*nj][0], bh[2*nj][1], bh[2*nj+1][0], bh[2*nj+1][1], s + R_BH + bo);
                ldsm4(bl[2*nj][0], bl[2*nj][1], bl[2*nj+1][0], bl[2*nj+1][1], s + R_BL + bo);
            }
#pragma unroll
            for (int mi = 0; mi < 2; ++mi)
#pragma unroll
                for (int nt = 0; nt < 4; ++nt) {
                    mma_f16(accm[mi][nt], ah[mi], bh[nt][0], bh[nt][1]);
                    mma_f16(accc[mi][nt], ah[mi], bl[nt][0], bl[nt][1]);
                    mma_f16(accc[mi][nt], al[mi], bh[nt][0], bh[nt][1]);
                }
        }

        if (more) stage(p ^ 1);
        __syncthreads();
        p ^= 1;
    }

    // ---- epilogue: combine main + scaled correction ----
    const int row0 = bb + warp_m * 32 + (lane >> 2);
    const int col0 = ob + warp_n * 32 + (lane & 3) * 2;
#pragma unroll
    for (int mi = 0; mi < 2; ++mi)
#pragma unroll
        for (int nt = 0; nt < 4; ++nt) {
            const int r = row0 + mi * 16;
            const int c = col0 + nt * 8;
            float v0 = fmaf(accc[mi][nt][0], LO_INV, accm[mi][nt][0]);
            float v1 = fmaf(accc[mi][nt][1], LO_INV, accm[mi][nt][1]);
            float v2 = fmaf(accc[mi][nt][2], LO_INV, accm[mi][nt][2]);
            float v3 = fmaf(accc[mi][nt][3], LO_INV, accm[mi][nt][3]);
            if (TRANS) {
                out[(size_t)c * BATCH + r]           = v0;
                out[(size_t)(c + 1) * BATCH + r]     = v1;
                out[(size_t)c * BATCH + r + 8]       = v2;
                out[(size_t)(c + 1) * BATCH + r + 8] = v3;
            } else {
                *(float2*)(out + (size_t)r * OUT + c)       = make_float2(v0, v1);
                *(float2*)(out + (size_t)(r + 8) * OUT + c) = make_float2(v2, v3);
            }
        }
}

// ---------------------------------------------------------------------------
__global__ void cvt_cm(const float* __restrict__ src, __half* __restrict__ h,
                       __half* __restrict__ l, int n)
{
    const int stride = gridDim.x * blockDim.x;
    for (int i = blockIdx.x * blockDim.x + threadIdx.x; i < n; i += stride) {
        unsigned short hv, lv;
        split2(src[i], hv, lv);
        h[i] = __ushort_as_half(hv);
        l[i] = __ushort_as_half(lv);
    }
}

// in[R][C] -> out[C][R]
__global__ void transpose_k(const float* __restrict__ in, float* __restrict__ out, int R, int C)
{
    __shared__ float tile[32][33];
    int c = blockIdx.x * 32 + threadIdx.x;
    int rb = blockIdx.y * 32;
#pragma unroll
    for (int j = 0; j < 32; j += 8)
        tile[threadIdx.y + j][threadIdx.x] = in[(size_t)(rb + threadIdx.y + j) * C + c];
    __syncthreads();
    int c2 = rb + threadIdx.x;
    int r2b = blockIdx.x * 32;
#pragma unroll
    for (int j = 0; j < 32; j += 8)
        out[(size_t)(r2b + threadIdx.y + j) * R + c2] = tile[threadIdx.x][threadIdx.y + j];
}

__global__ void kl_kernel(const float* __restrict__ c0, const float* __restrict__ l0, int n0,
                          const float* __restrict__ c1, const float* __restrict__ l1, int n1,
                          const float* __restrict__ c2, const float* __restrict__ l2, int n2,
                          float* __restrict__ part)
{
    float sacc = 0.0f;
    const int stride = gridDim.x * blockDim.x;
    const int t0 = blockIdx.x * blockDim.x + threadIdx.x;
    for (int i = t0; i < n0; i += stride) { float c = c0[i], l = l0[i]; sacc += __expf(l) + c * c - 1.0f - l; }
    for (int i = t0; i < n1; i += stride) { float c = c1[i], l = l1[i]; sacc += __expf(l) + c * c - 1.0f - l; }
    for (int i = t0; i < n2; i += stride) { float c = c2[i], l = l2[i]; sacc += __expf(l) + c * c - 1.0f - l; }
    __shared__ float sh[256];
    sh[threadIdx.x] = sacc;
    __syncthreads();
    for (int o = 128; o > 0; o >>= 1) {
        if (threadIdx.x < o) sh[threadIdx.x] += sh[threadIdx.x + o];
        __syncthreads();
    }
    if (threadIdx.x == 0) part[blockIdx.x] = 0.5f * sh[0];
}

__global__ void kl_final(const float* __restrict__ part, float* __restrict__ dst)
{
    __shared__ float sh[256];
    sh[threadIdx.x] = part[threadIdx.x];
    __syncthreads();
    for (int o = 128; o > 0; o >>= 1) {
        if (threadIdx.x < o) sh[threadIdx.x] += sh[threadIdx.x + o];
        __syncthreads();
    }
    if (threadIdx.x == 0) dst[0] = sh[0];
}

extern "C" void kernel_launch(void* const* d_in, const int* in_sizes, int n_in,
                              void* d_out, int out_size)
{
    const float* x   = (const float*)d_in[0];
    const float* cm0 = (const float*)d_in[1];
    const float* lv0 = (const float*)d_in[2];
    const float* cm1 = (const float*)d_in[3];
    const float* lv1 = (const float*)d_in[4];
    const float* cm2 = (const float*)d_in[5];
    const float* lv2 = (const float*)d_in[6];
    float* out = (float*)d_out;

    float *xt, *a1, *a2, *part;
    __half *cmh, *cml;
    cudaGetSymbolAddress((void**)&xt, g_xt);
    cudaGetSymbolAddress((void**)&a1, g_a1);
    cudaGetSymbolAddress((void**)&a2, g_a2);
    cudaGetSymbolAddress((void**)&part, g_part);
    cudaGetSymbolAddress((void**)&cmh, g_cmh);
    cudaGetSymbolAddress((void**)&cml, g_cml);

    cudaFuncSetAttribute(kan_hmma<1>, cudaFuncAttributeMaxDynamicSharedMemorySize, SMEM_TOT);
    cudaFuncSetAttribute(kan_hmma<0>, cudaFuncAttributeMaxDynamicSharedMemorySize, SMEM_TOT);

    // split cm into fp16 hi + scaled lo
    cvt_cm<<<512, 256>>>(cm0, cmh,           cml,           N0);
    cvt_cm<<<512, 256>>>(cm1, cmh + N0,      cml + N0,      N1);
    cvt_cm<<<512, 256>>>(cm2, cmh + N0 + N1, cml + N0 + N1, N2);

    // x [8192][256] -> xt [256][8192]
    transpose_k<<<dim3(8, 256), dim3(32, 8)>>>(x, xt, BATCH, 256);

    kan_hmma<1><<<dim3(4, 128), 256, SMEM_TOT>>>(xt, cmh,           cml,           a1, 256, 512);
    kan_hmma<1><<<dim3(4, 128), 256, SMEM_TOT>>>(a1, cmh + N0,      cml + N0,      a2, 512, 512);
    kan_hmma<0><<<dim3(2, 128), 256, SMEM_TOT>>>(a2, cmh + N0 + N1, cml + N0 + N1, out, 512, 256);

    if (out_size > KL_IDX) {
        kl_kernel<<<256, 256>>>(cm0, lv0, in_sizes[1], cm1, lv1, in_sizes[3],
                                cm2, lv2, in_sizes[5], part);
        kl_final<<<1, 256>>>(part, out + KL_IDX);
    }
}